// round 16
// baseline (speedup 1.0000x reference)
#include <cuda_runtime.h>
#include <cuda_fp16.h>
#include <cstdint>

// Problem dims (fixed)
constexpr int Bn = 2;
constexpr int Sn = 2048;
constexpr int Dn = 1024;
constexpr int Hn = 16;
constexpr int An = 64;
constexpr int Mrows = Bn * Sn;        // 4096
constexpr int HA = Hn * An;           // 1024

// Scratch (device globals; allocation-free), fp16 operands
// NOTE: g_qh is pre-scaled by 0.125 * log2(e) -> scores in log2 domain.
__device__ __align__(256) __half g_qh[(size_t)Bn * Hn * Sn * An];  // [b,h,s,a]
__device__ __align__(256) __half g_kh[(size_t)Bn * Hn * Sn * An];  // [b,h,s,a]
__device__ __align__(256) __half g_vh[(size_t)Bn * Hn * Sn * An];  // [b,h,a,s]  (transposed)
__device__ __align__(256) __half g_zh[(size_t)Bn * Sn * Hn * An];  // [b,s,h,a]
__device__ __align__(256) __half g_ath[(size_t)Mrows * Dn];        // residual fp16 [m][k]
__device__ __align__(256) __half g_wh[(size_t)4 * 1024 * 1024];    // weights fp16 [n][k]

// ---------------------------------------------------------------------------
// Helpers
// ---------------------------------------------------------------------------
__device__ __forceinline__ void cp_async16(uint32_t dst, const void* src) {
    asm volatile("cp.async.cg.shared.global [%0], [%1], 16;" :: "r"(dst), "l"(src) : "memory");
}
__device__ __forceinline__ uint32_t smem_u32(const void* p) {
    uint32_t a;
    asm("{ .reg .u64 t; cvta.to.shared.u64 t, %1; cvt.u32.u64 %0, t; }" : "=r"(a) : "l"(p));
    return a;
}
__device__ __forceinline__ void cp_commit() {
    asm volatile("cp.async.commit_group;" ::: "memory");
}
template <int N>
__device__ __forceinline__ void cp_wait() {
    asm volatile("cp.async.wait_group %0;" :: "n"(N) : "memory");
}
__device__ __forceinline__ void mma_f16_16n8k16(float* c, const uint32_t* a, const uint32_t* b) {
    asm volatile(
        "mma.sync.aligned.m16n8k16.row.col.f32.f16.f16.f32 "
        "{%0,%1,%2,%3}, {%4,%5,%6,%7}, {%8,%9}, {%0,%1,%2,%3};"
        : "+f"(c[0]), "+f"(c[1]), "+f"(c[2]), "+f"(c[3])
        : "r"(a[0]), "r"(a[1]), "r"(a[2]), "r"(a[3]), "r"(b[0]), "r"(b[1]));
}
__device__ __forceinline__ void ldsm_x4(uint32_t& r0, uint32_t& r1, uint32_t& r2, uint32_t& r3,
                                        uint32_t addr) {
    asm volatile("ldmatrix.sync.aligned.m8n8.x4.shared.b16 {%0,%1,%2,%3}, [%4];"
                 : "=r"(r0), "=r"(r1), "=r"(r2), "=r"(r3) : "r"(addr));
}
__device__ __forceinline__ uint32_t pack_h2(float x, float y) {
    __half2 h = __floats2half2_rn(x, y);
    return *(uint32_t*)&h;
}
__device__ __forceinline__ uint32_t ex2_h2(uint32_t x) {
    uint32_t r;
    asm("ex2.approx.f16x2 %0, %1;" : "=r"(r) : "r"(x));
    return r;
}
__device__ __forceinline__ float ex2_f32(float x) {
    float r;
    asm("ex2.approx.f32 %0, %1;" : "=f"(r) : "f"(x));
    return r;
}

// ---------------------------------------------------------------------------
// Prepass kernels (unchanged)
// ---------------------------------------------------------------------------
__global__ __launch_bounds__(256) void conv_resid_kernel(const float* __restrict__ src)
{
    constexpr int N4 = Mrows * Dn / 4;
    int idx = blockIdx.x * 256 + threadIdx.x;
    int stride = gridDim.x * 256;
    for (int i = idx; i < N4; i += stride) {
        float4 v = ((const float4*)src)[i];
        uint2 o;
        o.x = pack_h2(v.x, v.y);
        o.y = pack_h2(v.z, v.w);
        ((uint2*)g_ath)[i] = o;
    }
}

__global__ void transpose_qkv_kernel(const float* __restrict__ Wq,
                                     const float* __restrict__ Wk,
                                     const float* __restrict__ Wv)
{
    __shared__ float t[32][33];
    const int w = blockIdx.z / 16;
    const int h = blockIdx.z % 16;
    const float* S = (w == 0) ? Wq : (w == 1) ? Wk : Wv;
    S += (size_t)h * Dn * An;
    __half* D = g_wh + (size_t)w * (1024 * 1024) + (size_t)h * 64 * 1024;
    const int d0 = blockIdx.x * 32;
    const int a0 = blockIdx.y * 32;
    #pragma unroll
    for (int i = 0; i < 4; ++i)
        t[threadIdx.y + i * 8][threadIdx.x] = S[(size_t)(d0 + threadIdx.y + i * 8) * An + a0 + threadIdx.x];
    __syncthreads();
    #pragma unroll
    for (int i = 0; i < 4; ++i)
        D[(size_t)(a0 + threadIdx.y + i * 8) * 1024 + d0 + threadIdx.x] =
            __float2half_rn(t[threadIdx.x][threadIdx.y + i * 8]);
}

__global__ void transpose_wo_kernel(const float* __restrict__ Wo)
{
    __shared__ float t[32][33];
    __half* D = g_wh + (size_t)3 * (1024 * 1024);
    const int k0 = blockIdx.x * 32;
    const int n0 = blockIdx.y * 32;
    #pragma unroll
    for (int i = 0; i < 4; ++i)
        t[threadIdx.y + i * 8][threadIdx.x] = Wo[(size_t)(k0 + threadIdx.y + i * 8) * Dn + n0 + threadIdx.x];
    __syncthreads();
    #pragma unroll
    for (int i = 0; i < 4; ++i)
        D[(size_t)(n0 + threadIdx.y + i * 8) * 1024 + k0 + threadIdx.x] =
            __float2half_rn(t[threadIdx.x][threadIdx.y + i * 8]);
}

// ---------------------------------------------------------------------------
// fp16 GEMM: BM=128 BN=128 BK=64, 256 threads (8 warps: 2m x 4n, warp tile
// 64x32), NSTAGE=2, 2 CTAs/SM => 16 warps/SM. ldmatrix fragments.
// ---------------------------------------------------------------------------
constexpr int GP = 144;
constexpr int A_STG_B = 128 * GP;
constexpr int STG_B = 2 * A_STG_B;
constexpr int NSTAGE = 2;
constexpr int GEMM_SMEM = NSTAGE * STG_B;     // 73728
constexpr int KCHUNKS = 1024 / 64;
constexpr float Q_SCALE = 0.125f * 1.4426950408889634f;   // 1/sqrt(64) * log2(e)

template<int MODE>
__global__ __launch_bounds__(256, 2) void gemm_mma_kernel(
    const float* __restrict__ b0, const float* __restrict__ b1, const float* __restrict__ b2,
    float* __restrict__ outp)
{
    extern __shared__ __align__(16) uint32_t smem[];

    const int tid = threadIdx.x;
    const int lane = tid & 31;
    const int wid = tid >> 5;       // 0..7
    const int warp_m = wid & 1;     // 0..1 (64 rows)
    const int warp_n = wid >> 1;    // 0..3 (32 cols)
    const int grp = lane >> 2;
    const int qd = lane & 3;

    const int m0 = blockIdx.y * 128;
    const int n0 = blockIdx.x * 128;
    const int z = blockIdx.z;

    const __half* A = (MODE == 0) ? g_ath : g_zh;
    const __half* W = (MODE == 0) ? (g_wh + (size_t)z * (1024 * 1024))
                                  : (g_wh + (size_t)3 * (1024 * 1024));
    const float* bias = (MODE == 0) ? ((z == 0) ? b0 : (z == 1) ? b1 : b2) : b0;

    const uint32_t smem_base = smem_u32(smem);

    const uint32_t offA = (uint32_t)(warp_m * 64 + (lane & 15)) * GP + (uint32_t)(lane >> 4) * 16;
    const uint32_t offB = (uint32_t)(warp_n * 32 + ((lane >> 4) & 1) * 8 + (lane & 7)) * GP
                        + (uint32_t)((lane >> 3) & 1) * 16;

    auto produce = [&](int kc) {
        const int slot = kc & 1;
        const uint32_t sA = smem_base + (uint32_t)(slot * STG_B);
        const uint32_t sB = sA + (uint32_t)A_STG_B;
        #pragma unroll
        for (int i = 0; i < 4; ++i) {
            int task = i * 256 + tid;
            int r = task >> 3;
            int seg = task & 7;
            cp_async16(sA + (uint32_t)(r * GP + seg * 16),
                       A + (size_t)(m0 + r) * 1024 + kc * 64 + seg * 8);
        }
        #pragma unroll
        for (int i = 0; i < 4; ++i) {
            int task = i * 256 + tid;
            int n = task >> 3;
            int seg = task & 7;
            cp_async16(sB + (uint32_t)(n * GP + seg * 16),
                       W + (size_t)(n0 + n) * 1024 + kc * 64 + seg * 8);
        }
        cp_commit();
    };

    float acc[4][4][4];
    #pragma unroll
    for (int mt = 0; mt < 4; ++mt)
        #pragma unroll
        for (int nt = 0; nt < 4; ++nt)
            #pragma unroll
            for (int e = 0; e < 4; ++e) acc[mt][nt][e] = 0.0f;

    produce(0);
    produce(1);

    for (int kc = 0; kc < KCHUNKS; ++kc) {
        cp_wait<1>();
        __syncthreads();

        const uint32_t sA = smem_base + (uint32_t)((kc & 1) * STG_B);
        const uint32_t sB = sA + (uint32_t)A_STG_B;

        #pragma unroll
        for (int ks = 0; ks < 4; ++ks) {
            uint32_t af[4][4], bf[4][2];
            #pragma unroll
            for (int mt = 0; mt < 4; ++mt)
                ldsm_x4(af[mt][0], af[mt][1], af[mt][2], af[mt][3],
                        sA + offA + (uint32_t)(mt * 16 * GP + ks * 32));
            #pragma unroll
            for (int ntp = 0; ntp < 2; ++ntp) {
                uint32_t t0, t1, t2, t3;
                ldsm_x4(t0, t1, t2, t3, sB + offB + (uint32_t)(ntp * 16 * GP + ks * 32));
                bf[2 * ntp][0] = t0; bf[2 * ntp][1] = t1;
                bf[2 * ntp + 1][0] = t2; bf[2 * ntp + 1][1] = t3;
            }
            #pragma unroll
            for (int mt = 0; mt < 4; ++mt)
                #pragma unroll
                for (int nt = 0; nt < 4; ++nt)
                    mma_f16_16n8k16(acc[mt][nt], af[mt], bf[nt]);
        }

        __syncthreads();
        if (kc + 2 < KCHUNKS) produce(kc + 2);
    }

    #pragma unroll
    for (int mt = 0; mt < 4; ++mt) {
        #pragma unroll
        for (int half = 0; half < 2; ++half) {
            const int m = m0 + warp_m * 64 + mt * 16 + grp + half * 8;
            #pragma unroll
            for (int nt = 0; nt < 4; ++nt) {
                const int n = n0 + warp_n * 32 + nt * 8 + qd * 2;
                float vx = acc[mt][nt][half * 2 + 0] + bias[n];
                float vy = acc[mt][nt][half * 2 + 1] + bias[n + 1];
                if (MODE == 0) {
                    const int b = m >> 11;
                    const int s = m & 2047;
                    const int h = n >> 6;
                    const int a = n & 63;
                    if (z == 0) {
                        vx *= Q_SCALE; vy *= Q_SCALE;   // log2-domain scores
                        *(uint32_t*)&g_qh[(((size_t)b * Hn + h) * Sn + s) * An + a] = pack_h2(vx, vy);
                    } else if (z == 1) {
                        *(uint32_t*)&g_kh[(((size_t)b * Hn + h) * Sn + s) * An + a] = pack_h2(vx, vy);
                    } else {
                        __half* Vd = g_vh + (((size_t)b * Hn + h) * An) * Sn;
                        Vd[(size_t)a * Sn + s] = __float2half_rn(vx);
                        Vd[(size_t)(a + 1) * Sn + s] = __float2half_rn(vy);
                    }
                } else {
                    float2 v2 = {vx, vy};
                    *(float2*)&outp[(size_t)m * Dn + n] = v2;
                }
            }
        }
    }
}

// ---------------------------------------------------------------------------
// Causal flash attention (unchanged from R15, proven): 128-thread CTAs over
// 64-row q-tiles, 3 CTAs/SM; log2-domain ex2.f16x2 softmax; P in registers.
// ---------------------------------------------------------------------------
constexpr int K_STG_B = 64 * 144;       // 9216
constexpr int KV_STG_B = 2 * K_STG_B;   // 18432
constexpr int NSTAGE_F = 3;
constexpr int FLASH_SMEM_BYTES = NSTAGE_F * KV_STG_B;   // 55296

__global__ __launch_bounds__(128, 3) void flash_mma_kernel()
{
    extern __shared__ uint32_t sm_u[];

    const int tid = threadIdx.x;
    const int lane = tid & 31;
    const int wid = tid >> 5;       // 0..3
    const int grp = lane >> 2;
    const int qd = lane & 3;

    const int bh = blockIdx.y;
    const size_t base = (size_t)bh * Sn * An;
    const int q0 = blockIdx.x * 64;        // 64-row q tile
    const uint32_t smem_base = smem_u32(sm_u);

    const uint32_t offQ = (uint32_t)(wid * 16 + (lane & 15)) * 144 + (uint32_t)(lane >> 4) * 16;
    const uint32_t offKV = (uint32_t)(((lane >> 4) & 1) * 8 + (lane & 7)) * 144
                         + (uint32_t)((lane >> 3) & 1) * 16;

    auto produce_body = [&](int t) {
        const uint32_t sK = smem_base + (uint32_t)((t % NSTAGE_F) * KV_STG_B);
        const uint32_t sV = sK + (uint32_t)K_STG_B;
        const int j0 = t * 64;
        #pragma unroll
        for (int i = 0; i < 4; ++i) {
            int idx = i * 128 + tid;
            int r = idx >> 3;
            int seg = idx & 7;
            cp_async16(sK + (uint32_t)(r * 144 + seg * 16),
                       g_kh + base + (size_t)(j0 + r) * An + seg * 8);
        }
        #pragma unroll
        for (int i = 0; i < 4; ++i) {
            int idx = i * 128 + tid;
            int a = idx >> 3;
            int seg = idx & 7;
            cp_async16(sV + (uint32_t)(a * 144 + seg * 16),
                       g_vh + base + (size_t)a * Sn + j0 + seg * 8);
        }
    };

    // prologue
    produce_body(0);
    cp_commit();
    if (q0 >= 64) produce_body(1);
    {
        const uint32_t sQb = smem_base + (uint32_t)(2 * KV_STG_B);
        #pragma unroll
        for (int i = 0; i < 4; ++i) {
            int idx = i * 128 + tid;
            int r = idx >> 3;
            int seg = idx & 7;
            cp_async16(sQb + (uint32_t)(r * 144 + seg * 16),
                       g_qh + base + (size_t)(q0 + r) * An + seg * 8);
        }
    }
    cp_commit();
    cp_wait<0>();
    __syncthreads();

    uint32_t qf[4][4];
    #pragma unroll
    for (int ks = 0; ks < 4; ++ks)
        ldsm_x4(qf[ks][0], qf[ks][1], qf[ks][2], qf[ks][3],
                smem_base + 2 * KV_STG_B + offQ + ks * 32);

    const int r0 = wid * 16 + grp;
    float m0r = -1e30f, m1r = -1e30f, l0r = 0.0f, l1r = 0.0f;
    float o[8][4];
    #pragma unroll
    for (int nt = 0; nt < 8; ++nt)
        #pragma unroll
        for (int e = 0; e < 4; ++e) o[nt][e] = 0.0f;

    const int grow0 = q0 + r0;
    const int grow1 = grow0 + 8;
    const int ntiles = q0 / 64 + 1;

    for (int t = 0; t < ntiles; ++t) {
        cp_wait<1>();
        __syncthreads();
        if (t + 2 < ntiles) {
            produce_body(t + 2);
            cp_commit();
        }

        const uint32_t sK_b = smem_base + (uint32_t)((t % NSTAGE_F) * KV_STG_B);
        const uint32_t sV_b = sK_b + (uint32_t)K_STG_B;
        const int j0 = t * 64;

        float sacc[8][4];
        #pragma unroll
        for (int nt = 0; nt < 8; ++nt)
            #pragma unroll
            for (int e = 0; e < 4; ++e) sacc[nt][e] = 0.0f;

        #pragma unroll
        for (int ks = 0; ks < 4; ++ks) {
            uint32_t kf[8][2];
            #pragma unroll
            for (int ntp = 0; ntp < 4; ++ntp) {
                uint32_t t0, t1, t2, t3;
                ldsm_x4(t0, t1, t2, t3, sK_b + offKV + (uint32_t)(ntp * 16 * 144 + ks * 32));
                kf[2 * ntp][0] = t0; kf[2 * ntp][1] = t1;
                kf[2 * ntp + 1][0] = t2; kf[2 * ntp + 1][1] = t3;
            }
            #pragma unroll
            for (int nt = 0; nt < 8; ++nt)
                mma_f16_16n8k16(sacc[nt], qf[ks], kf[nt]);
        }

        if (j0 + 63 > q0) {
            #pragma unroll
            for (int nt = 0; nt < 8; ++nt) {
                int c = j0 + nt * 8 + qd * 2;
                if (c > grow0)     sacc[nt][0] = -1e30f;
                if (c + 1 > grow0) sacc[nt][1] = -1e30f;
                if (c > grow1)     sacc[nt][2] = -1e30f;
                if (c + 1 > grow1) sacc[nt][3] = -1e30f;
            }
        }

        float rm0 = -1e30f, rm1 = -1e30f;
        #pragma unroll
        for (int nt = 0; nt < 8; ++nt) {
            rm0 = fmaxf(rm0, fmaxf(sacc[nt][0], sacc[nt][1]));
            rm1 = fmaxf(rm1, fmaxf(sacc[nt][2], sacc[nt][3]));
        }
        rm0 = fmaxf(rm0, __shfl_xor_sync(0xffffffffu, rm0, 1));
        rm0 = fmaxf(rm0, __shfl_xor_sync(0xffffffffu, rm0, 2));
        rm1 = fmaxf(rm1, __shfl_xor_sync(0xffffffffu, rm1, 1));
        rm1 = fmaxf(rm1, __shfl_xor_sync(0xffffffffu, rm1, 2));

        float mn0 = fmaxf(m0r, rm0);
        float mn1 = fmaxf(m1r, rm1);
        float corr0 = ex2_f32(m0r - mn0);
        float corr1 = ex2_f32(m1r - mn1);
        m0r = mn0; m1r = mn1;

        uint32_t pf[4][4];
        float rs0 = 0.0f, rs1 = 0.0f;
        #pragma unroll
        for (int nt = 0; nt < 8; ++nt) {
            uint32_t x01 = pack_h2(sacc[nt][0] - mn0, sacc[nt][1] - mn0);
            uint32_t x23 = pack_h2(sacc[nt][2] - mn1, sacc[nt][3] - mn1);
            uint32_t p01 = ex2_h2(x01);
            uint32_t p23 = ex2_h2(x23);
            pf[nt >> 1][(nt & 1) * 2 + 0] = p01;
            pf[nt >> 1][(nt & 1) * 2 + 1] = p23;
            float2 f01 = __half22float2(*(__half2*)&p01);
            float2 f23 = __half22float2(*(__half2*)&p23);
            rs0 += f01.x + f01.y;
            rs1 += f23.x + f23.y;
        }
        rs0 += __shfl_xor_sync(0xffffffffu, rs0, 1);
        rs0 += __shfl_xor_sync(0xffffffffu, rs0, 2);
        rs1 += __shfl_xor_sync(0xffffffffu, rs1, 1);
        rs1 += __shfl_xor_sync(0xffffffffu, rs1, 2);
        l0r = l0r * corr0 + rs0;
        l1r = l1r * corr1 + rs1;

        #pragma unroll
        for (int nt = 0; nt < 8; ++nt) {
            o[nt][0] *= corr0;
            o[nt][1] *= corr0;
            o[nt][2] *= corr1;
            o[nt][3] *= corr1;
        }

        #pragma unroll
        for (int ks = 0; ks < 4; ++ks) {
            uint32_t vf[8][2];
            #pragma unroll
            for (int ntp = 0; ntp < 4; ++ntp) {
                uint32_t t0, t1, t2, t3;
                ldsm_x4(t0, t1, t2, t3, sV_b + offKV + (uint32_t)(ntp * 16 * 144 + ks * 32));
                vf[2 * ntp][0] = t0; vf[2 * ntp][1] = t1;
                vf[2 * ntp + 1][0] = t2; vf[2 * ntp + 1][1] = t3;
            }
            #pragma unroll
            for (int nt = 0; nt < 8; ++nt)
                mma_f16_16n8k16(o[nt], pf[ks], vf[nt]);
        }
    }

    const int b = bh >> 4;
    const int h = bh & 15;
    const float inv0 = 1.0f / l0r;
    const float inv1 = 1.0f / l1r;
    #pragma unroll
    for (int nt = 0; nt < 8; ++nt) {
        const int a = nt * 8 + qd * 2;
        *(uint32_t*)&g_zh[(((size_t)b * Sn + grow0) * Hn + h) * An + a] =
            pack_h2(o[nt][0] * inv0, o[nt][1] * inv0);
        *(uint32_t*)&g_zh[(((size_t)b * Sn + grow1) * Hn + h) * An + a] =
            pack_h2(o[nt][2] * inv1, o[nt][3] * inv1);
    }
}

// ---------------------------------------------------------------------------
extern "C" void kernel_launch(void* const* d_in, const int* in_sizes, int n_in,
                              void* d_out, int out_size)
{
    const float* residual = (const float*)d_in[0];
    const float* Wq = (const float*)d_in[1];
    const float* Wk = (const float*)d_in[2];
    const float* Wv = (const float*)d_in[3];
    const float* Wo = (const float*)d_in[4];
    const float* bq = (const float*)d_in[5];
    const float* bk = (const float*)d_in[6];
    const float* bv = (const float*)d_in[7];
    const float* bo = (const float*)d_in[8];
    float* out = (float*)d_out;

    cudaFuncSetAttribute(flash_mma_kernel, cudaFuncAttributeMaxDynamicSharedMemorySize,
                         FLASH_SMEM_BYTES);
    cudaFuncSetAttribute(gemm_mma_kernel<0>, cudaFuncAttributeMaxDynamicSharedMemorySize,
                         GEMM_SMEM);
    cudaFuncSetAttribute(gemm_mma_kernel<1>, cudaFuncAttributeMaxDynamicSharedMemorySize,
                         GEMM_SMEM);

    // 0) fp16 prepass
    conv_resid_kernel<<<1024, 256>>>(residual);
    transpose_qkv_kernel<<<dim3(1024 / 32, 64 / 32, 48), dim3(32, 8)>>>(Wq, Wk, Wv);
    transpose_wo_kernel<<<dim3(32, 32), dim3(32, 8)>>>(Wo);

    // 1) QKV projections (256 threads, 8 warps, 16 warps/SM)
    gemm_mma_kernel<0><<<dim3(HA / 128, Mrows / 128, 3), 256, GEMM_SMEM>>>(
        bq, bk, bv, nullptr);

    // 2) Causal flash attention
    flash_mma_kernel<<<dim3(Sn / 64, Bn * Hn), 128, FLASH_SMEM_BYTES>>>();

    // 3) Output projection
    gemm_mma_kernel<1><<<dim3(Dn / 128, Mrows / 128, 1), 256, GEMM_SMEM>>>(
        bo, nullptr, nullptr, out);
}

// round 17
// speedup vs baseline: 1.0212x; 1.0212x over previous
#include <cuda_runtime.h>
#include <cuda_fp16.h>
#include <cstdint>

// Problem dims (fixed)
constexpr int Bn = 2;
constexpr int Sn = 2048;
constexpr int Dn = 1024;
constexpr int Hn = 16;
constexpr int An = 64;
constexpr int Mrows = Bn * Sn;        // 4096
constexpr int HA = Hn * An;           // 1024

// Scratch (device globals; allocation-free), fp16 operands
// NOTE: g_qh is pre-scaled by 0.125 * log2(e) -> scores in log2 domain.
__device__ __align__(256) __half g_qh[(size_t)Bn * Hn * Sn * An];  // [b,h,s,a]
__device__ __align__(256) __half g_kh[(size_t)Bn * Hn * Sn * An];  // [b,h,s,a]
__device__ __align__(256) __half g_vh[(size_t)Bn * Hn * Sn * An];  // [b,h,a,s]  (transposed)
__device__ __align__(256) __half g_zh[(size_t)Bn * Sn * Hn * An];  // [b,s,h,a]
__device__ __align__(256) __half g_ath[(size_t)Mrows * Dn];        // residual fp16 [m][k]
__device__ __align__(256) __half g_wh[(size_t)4 * 1024 * 1024];    // weights fp16 [n][k]

// ---------------------------------------------------------------------------
// Helpers
// ---------------------------------------------------------------------------
__device__ __forceinline__ void cp_async16(uint32_t dst, const void* src) {
    asm volatile("cp.async.cg.shared.global [%0], [%1], 16;" :: "r"(dst), "l"(src) : "memory");
}
__device__ __forceinline__ uint32_t smem_u32(const void* p) {
    uint32_t a;
    asm("{ .reg .u64 t; cvta.to.shared.u64 t, %1; cvt.u32.u64 %0, t; }" : "=r"(a) : "l"(p));
    return a;
}
__device__ __forceinline__ void cp_commit() {
    asm volatile("cp.async.commit_group;" ::: "memory");
}
template <int N>
__device__ __forceinline__ void cp_wait() {
    asm volatile("cp.async.wait_group %0;" :: "n"(N) : "memory");
}
__device__ __forceinline__ void mma_f16_16n8k16(float* c, const uint32_t* a, const uint32_t* b) {
    asm volatile(
        "mma.sync.aligned.m16n8k16.row.col.f32.f16.f16.f32 "
        "{%0,%1,%2,%3}, {%4,%5,%6,%7}, {%8,%9}, {%0,%1,%2,%3};"
        : "+f"(c[0]), "+f"(c[1]), "+f"(c[2]), "+f"(c[3])
        : "r"(a[0]), "r"(a[1]), "r"(a[2]), "r"(a[3]), "r"(b[0]), "r"(b[1]));
}
__device__ __forceinline__ void ldsm_x4(uint32_t& r0, uint32_t& r1, uint32_t& r2, uint32_t& r3,
                                        uint32_t addr) {
    asm volatile("ldmatrix.sync.aligned.m8n8.x4.shared.b16 {%0,%1,%2,%3}, [%4];"
                 : "=r"(r0), "=r"(r1), "=r"(r2), "=r"(r3) : "r"(addr));
}
__device__ __forceinline__ uint32_t pack_h2(float x, float y) {
    __half2 h = __floats2half2_rn(x, y);
    return *(uint32_t*)&h;
}
__device__ __forceinline__ uint32_t ex2_h2(uint32_t x) {
    uint32_t r;
    asm("ex2.approx.f16x2 %0, %1;" : "=r"(r) : "r"(x));
    return r;
}
__device__ __forceinline__ float ex2_f32(float x) {
    float r;
    asm("ex2.approx.f32 %0, %1;" : "=f"(r) : "f"(x));
    return r;
}

// ---------------------------------------------------------------------------
// Prepass 1: residual fp32 -> fp16 [m][k]
// ---------------------------------------------------------------------------
__global__ __launch_bounds__(256) void conv_resid_kernel(const float* __restrict__ src)
{
    constexpr int N4 = Mrows * Dn / 4;
    int idx = blockIdx.x * 256 + threadIdx.x;
    int stride = gridDim.x * 256;
    for (int i = idx; i < N4; i += stride) {
        float4 v = ((const float4*)src)[i];
        uint2 o;
        o.x = pack_h2(v.x, v.y);
        o.y = pack_h2(v.z, v.w);
        ((uint2*)g_ath)[i] = o;
    }
}

// ---------------------------------------------------------------------------
// Prepass 2 (fused): all 4 weight transposes -> g_wh[w][n][k] fp16.
// z in [0,48): qkv, w=z/16, h=z%16, tile (d0=x*32, a0=y*32)  [y in 0..1]
// z in [48,64): Wo,  n-tile = (z-48)*2 + y (0..31), k-tile = x (0..31)
// grid (32, 2, 64), block (32, 8)
// ---------------------------------------------------------------------------
__global__ void transpose_w_kernel(const float* __restrict__ Wq,
                                   const float* __restrict__ Wk,
                                   const float* __restrict__ Wv,
                                   const float* __restrict__ Wo)
{
    __shared__ float t[32][33];
    const int z = blockIdx.z;

    if (z < 48) {
        const int w = z / 16;
        const int h = z % 16;
        const float* S = (w == 0) ? Wq : (w == 1) ? Wk : Wv;
        S += (size_t)h * Dn * An;
        __half* D = g_wh + (size_t)w * (1024 * 1024) + (size_t)h * 64 * 1024;
        const int d0 = blockIdx.x * 32;
        const int a0 = blockIdx.y * 32;
        #pragma unroll
        for (int i = 0; i < 4; ++i)
            t[threadIdx.y + i * 8][threadIdx.x] =
                S[(size_t)(d0 + threadIdx.y + i * 8) * An + a0 + threadIdx.x];
        __syncthreads();
        #pragma unroll
        for (int i = 0; i < 4; ++i)
            D[(size_t)(a0 + threadIdx.y + i * 8) * 1024 + d0 + threadIdx.x] =
                __float2half_rn(t[threadIdx.x][threadIdx.y + i * 8]);
    } else {
        __half* D = g_wh + (size_t)3 * (1024 * 1024);
        const int k0 = blockIdx.x * 32;
        const int n0 = ((z - 48) * 2 + blockIdx.y) * 32;
        #pragma unroll
        for (int i = 0; i < 4; ++i)
            t[threadIdx.y + i * 8][threadIdx.x] =
                Wo[(size_t)(k0 + threadIdx.y + i * 8) * Dn + n0 + threadIdx.x];
        __syncthreads();
        #pragma unroll
        for (int i = 0; i < 4; ++i)
            D[(size_t)(n0 + threadIdx.y + i * 8) * 1024 + k0 + threadIdx.x] =
                __float2half_rn(t[threadIdx.x][threadIdx.y + i * 8]);
    }
}

// ---------------------------------------------------------------------------
// fp16 GEMM (R15 proven config): BM=128 BN=128 BK=64, 128 threads (4 warps
// 2m x 2n, warp tile 64x64), NSTAGE=2, 3 CTAs/SM. ldmatrix fragments.
// ---------------------------------------------------------------------------
constexpr int GP = 144;
constexpr int A_STG_B = 128 * GP;
constexpr int STG_B = 2 * A_STG_B;
constexpr int NSTAGE = 2;
constexpr int GEMM_SMEM = NSTAGE * STG_B;     // 73728
constexpr int KCHUNKS = 1024 / 64;
constexpr float Q_SCALE = 0.125f * 1.4426950408889634f;   // 1/sqrt(64) * log2(e)

template<int MODE>
__global__ __launch_bounds__(128, 3) void gemm_mma_kernel(
    const float* __restrict__ b0, const float* __restrict__ b1, const float* __restrict__ b2,
    float* __restrict__ outp)
{
    extern __shared__ __align__(16) uint32_t smem[];

    const int tid = threadIdx.x;
    const int lane = tid & 31;
    const int wid = tid >> 5;
    const int warp_m = wid & 1;
    const int warp_n = wid >> 1;
    const int grp = lane >> 2;
    const int qd = lane & 3;

    const int m0 = blockIdx.y * 128;
    const int n0 = blockIdx.x * 128;
    const int z = blockIdx.z;

    const __half* A = (MODE == 0) ? g_ath : g_zh;
    const __half* W = (MODE == 0) ? (g_wh + (size_t)z * (1024 * 1024))
                                  : (g_wh + (size_t)3 * (1024 * 1024));
    const float* bias = (MODE == 0) ? ((z == 0) ? b0 : (z == 1) ? b1 : b2) : b0;

    const uint32_t smem_base = smem_u32(smem);

    const uint32_t offA = (uint32_t)(warp_m * 64 + (lane & 15)) * GP + (uint32_t)(lane >> 4) * 16;
    const uint32_t offB = (uint32_t)(warp_n * 64 + ((lane >> 4) & 1) * 8 + (lane & 7)) * GP
                        + (uint32_t)((lane >> 3) & 1) * 16;

    auto produce = [&](int kc) {
        const int slot = kc & 1;
        const uint32_t sA = smem_base + (uint32_t)(slot * STG_B);
        const uint32_t sB = sA + (uint32_t)A_STG_B;
        #pragma unroll
        for (int i = 0; i < 8; ++i) {
            int task = i * 128 + tid;
            int r = task >> 3;
            int seg = task & 7;
            cp_async16(sA + (uint32_t)(r * GP + seg * 16),
                       A + (size_t)(m0 + r) * 1024 + kc * 64 + seg * 8);
        }
        #pragma unroll
        for (int i = 0; i < 8; ++i) {
            int task = i * 128 + tid;
            int n = task >> 3;
            int seg = task & 7;
            cp_async16(sB + (uint32_t)(n * GP + seg * 16),
                       W + (size_t)(n0 + n) * 1024 + kc * 64 + seg * 8);
        }
        cp_commit();
    };

    float acc[4][8][4];
    #pragma unroll
    for (int mt = 0; mt < 4; ++mt)
        #pragma unroll
        for (int nt = 0; nt < 8; ++nt)
            #pragma unroll
            for (int e = 0; e < 4; ++e) acc[mt][nt][e] = 0.0f;

    produce(0);
    produce(1);

    for (int kc = 0; kc < KCHUNKS; ++kc) {
        cp_wait<1>();
        __syncthreads();

        const uint32_t sA = smem_base + (uint32_t)((kc & 1) * STG_B);
        const uint32_t sB = sA + (uint32_t)A_STG_B;

        #pragma unroll
        for (int ks = 0; ks < 4; ++ks) {
            uint32_t af[4][4], bf[8][2];
            #pragma unroll
            for (int mt = 0; mt < 4; ++mt)
                ldsm_x4(af[mt][0], af[mt][1], af[mt][2], af[mt][3],
                        sA + offA + (uint32_t)(mt * 16 * GP + ks * 32));
            #pragma unroll
            for (int ntp = 0; ntp < 4; ++ntp) {
                uint32_t t0, t1, t2, t3;
                ldsm_x4(t0, t1, t2, t3, sB + offB + (uint32_t)(ntp * 16 * GP + ks * 32));
                bf[2 * ntp][0] = t0; bf[2 * ntp][1] = t1;
                bf[2 * ntp + 1][0] = t2; bf[2 * ntp + 1][1] = t3;
            }
            #pragma unroll
            for (int mt = 0; mt < 4; ++mt)
                #pragma unroll
                for (int nt = 0; nt < 8; ++nt)
                    mma_f16_16n8k16(acc[mt][nt], af[mt], bf[nt]);
        }

        __syncthreads();
        if (kc + 2 < KCHUNKS) produce(kc + 2);
    }

    #pragma unroll
    for (int mt = 0; mt < 4; ++mt) {
        #pragma unroll
        for (int half = 0; half < 2; ++half) {
            const int m = m0 + warp_m * 64 + mt * 16 + grp + half * 8;
            #pragma unroll
            for (int nt = 0; nt < 8; ++nt) {
                const int n = n0 + warp_n * 64 + nt * 8 + qd * 2;
                float vx = acc[mt][nt][half * 2 + 0] + bias[n];
                float vy = acc[mt][nt][half * 2 + 1] + bias[n + 1];
                if (MODE == 0) {
                    const int b = m >> 11;
                    const int s = m & 2047;
                    const int h = n >> 6;
                    const int a = n & 63;
                    if (z == 0) {
                        vx *= Q_SCALE; vy *= Q_SCALE;   // log2-domain scores
                        *(uint32_t*)&g_qh[(((size_t)b * Hn + h) * Sn + s) * An + a] = pack_h2(vx, vy);
                    } else if (z == 1) {
                        *(uint32_t*)&g_kh[(((size_t)b * Hn + h) * Sn + s) * An + a] = pack_h2(vx, vy);
                    } else {
                        __half* Vd = g_vh + (((size_t)b * Hn + h) * An) * Sn;
                        Vd[(size_t)a * Sn + s] = __float2half_rn(vx);
                        Vd[(size_t)(a + 1) * Sn + s] = __float2half_rn(vy);
                    }
                } else {
                    float2 v2 = {vx, vy};
                    *(float2*)&outp[(size_t)m * Dn + n] = v2;
                }
            }
        }
    }
}

// ---------------------------------------------------------------------------
// Causal flash attention (unchanged from R15, proven): 128-thread CTAs over
// 64-row q-tiles, 3 CTAs/SM; log2-domain ex2.f16x2 softmax; P in registers.
// ---------------------------------------------------------------------------
constexpr int K_STG_B = 64 * 144;       // 9216
constexpr int KV_STG_B = 2 * K_STG_B;   // 18432
constexpr int NSTAGE_F = 3;
constexpr int FLASH_SMEM_BYTES = NSTAGE_F * KV_STG_B;   // 55296

__global__ __launch_bounds__(128, 3) void flash_mma_kernel()
{
    extern __shared__ uint32_t sm_u[];

    const int tid = threadIdx.x;
    const int lane = tid & 31;
    const int wid = tid >> 5;       // 0..3
    const int grp = lane >> 2;
    const int qd = lane & 3;

    const int bh = blockIdx.y;
    const size_t base = (size_t)bh * Sn * An;
    const int q0 = blockIdx.x * 64;        // 64-row q tile
    const uint32_t smem_base = smem_u32(sm_u);

    const uint32_t offQ = (uint32_t)(wid * 16 + (lane & 15)) * 144 + (uint32_t)(lane >> 4) * 16;
    const uint32_t offKV = (uint32_t)(((lane >> 4) & 1) * 8 + (lane & 7)) * 144
                         + (uint32_t)((lane >> 3) & 1) * 16;

    auto produce_body = [&](int t) {
        const uint32_t sK = smem_base + (uint32_t)((t % NSTAGE_F) * KV_STG_B);
        const uint32_t sV = sK + (uint32_t)K_STG_B;
        const int j0 = t * 64;
        #pragma unroll
        for (int i = 0; i < 4; ++i) {
            int idx = i * 128 + tid;
            int r = idx >> 3;
            int seg = idx & 7;
            cp_async16(sK + (uint32_t)(r * 144 + seg * 16),
                       g_kh + base + (size_t)(j0 + r) * An + seg * 8);
        }
        #pragma unroll
        for (int i = 0; i < 4; ++i) {
            int idx = i * 128 + tid;
            int a = idx >> 3;
            int seg = idx & 7;
            cp_async16(sV + (uint32_t)(a * 144 + seg * 16),
                       g_vh + base + (size_t)a * Sn + j0 + seg * 8);
        }
    };

    // prologue
    produce_body(0);
    cp_commit();
    if (q0 >= 64) produce_body(1);
    {
        const uint32_t sQb = smem_base + (uint32_t)(2 * KV_STG_B);
        #pragma unroll
        for (int i = 0; i < 4; ++i) {
            int idx = i * 128 + tid;
            int r = idx >> 3;
            int seg = idx & 7;
            cp_async16(sQb + (uint32_t)(r * 144 + seg * 16),
                       g_qh + base + (size_t)(q0 + r) * An + seg * 8);
        }
    }
    cp_commit();
    cp_wait<0>();
    __syncthreads();

    uint32_t qf[4][4];
    #pragma unroll
    for (int ks = 0; ks < 4; ++ks)
        ldsm_x4(qf[ks][0], qf[ks][1], qf[ks][2], qf[ks][3],
                smem_base + 2 * KV_STG_B + offQ + ks * 32);

    const int r0 = wid * 16 + grp;
    float m0r = -1e30f, m1r = -1e30f, l0r = 0.0f, l1r = 0.0f;
    float o[8][4];
    #pragma unroll
    for (int nt = 0; nt < 8; ++nt)
        #pragma unroll
        for (int e = 0; e < 4; ++e) o[nt][e] = 0.0f;

    const int grow0 = q0 + r0;
    const int grow1 = grow0 + 8;
    const int ntiles = q0 / 64 + 1;

    for (int t = 0; t < ntiles; ++t) {
        cp_wait<1>();
        __syncthreads();
        if (t + 2 < ntiles) {
            produce_body(t + 2);
            cp_commit();
        }

        const uint32_t sK_b = smem_base + (uint32_t)((t % NSTAGE_F) * KV_STG_B);
        const uint32_t sV_b = sK_b + (uint32_t)K_STG_B;
        const int j0 = t * 64;

        float sacc[8][4];
        #pragma unroll
        for (int nt = 0; nt < 8; ++nt)
            #pragma unroll
            for (int e = 0; e < 4; ++e) sacc[nt][e] = 0.0f;

        #pragma unroll
        for (int ks = 0; ks < 4; ++ks) {
            uint32_t kf[8][2];
            #pragma unroll
            for (int ntp = 0; ntp < 4; ++ntp) {
                uint32_t t0, t1, t2, t3;
                ldsm_x4(t0, t1, t2, t3, sK_b + offKV + (uint32_t)(ntp * 16 * 144 + ks * 32));
                kf[2 * ntp][0] = t0; kf[2 * ntp][1] = t1;
                kf[2 * ntp + 1][0] = t2; kf[2 * ntp + 1][1] = t3;
            }
            #pragma unroll
            for (int nt = 0; nt < 8; ++nt)
                mma_f16_16n8k16(sacc[nt], qf[ks], kf[nt]);
        }

        if (j0 + 63 > q0) {
            #pragma unroll
            for (int nt = 0; nt < 8; ++nt) {
                int c = j0 + nt * 8 + qd * 2;
                if (c > grow0)     sacc[nt][0] = -1e30f;
                if (c + 1 > grow0) sacc[nt][1] = -1e30f;
                if (c > grow1)     sacc[nt][2] = -1e30f;
                if (c + 1 > grow1) sacc[nt][3] = -1e30f;
            }
        }

        float rm0 = -1e30f, rm1 = -1e30f;
        #pragma unroll
        for (int nt = 0; nt < 8; ++nt) {
            rm0 = fmaxf(rm0, fmaxf(sacc[nt][0], sacc[nt][1]));
            rm1 = fmaxf(rm1, fmaxf(sacc[nt][2], sacc[nt][3]));
        }
        rm0 = fmaxf(rm0, __shfl_xor_sync(0xffffffffu, rm0, 1));
        rm0 = fmaxf(rm0, __shfl_xor_sync(0xffffffffu, rm0, 2));
        rm1 = fmaxf(rm1, __shfl_xor_sync(0xffffffffu, rm1, 1));
        rm1 = fmaxf(rm1, __shfl_xor_sync(0xffffffffu, rm1, 2));

        float mn0 = fmaxf(m0r, rm0);
        float mn1 = fmaxf(m1r, rm1);
        float corr0 = ex2_f32(m0r - mn0);
        float corr1 = ex2_f32(m1r - mn1);
        m0r = mn0; m1r = mn1;

        uint32_t pf[4][4];
        float rs0 = 0.0f, rs1 = 0.0f;
        #pragma unroll
        for (int nt = 0; nt < 8; ++nt) {
            uint32_t x01 = pack_h2(sacc[nt][0] - mn0, sacc[nt][1] - mn0);
            uint32_t x23 = pack_h2(sacc[nt][2] - mn1, sacc[nt][3] - mn1);
            uint32_t p01 = ex2_h2(x01);
            uint32_t p23 = ex2_h2(x23);
            pf[nt >> 1][(nt & 1) * 2 + 0] = p01;
            pf[nt >> 1][(nt & 1) * 2 + 1] = p23;
            float2 f01 = __half22float2(*(__half2*)&p01);
            float2 f23 = __half22float2(*(__half2*)&p23);
            rs0 += f01.x + f01.y;
            rs1 += f23.x + f23.y;
        }
        rs0 += __shfl_xor_sync(0xffffffffu, rs0, 1);
        rs0 += __shfl_xor_sync(0xffffffffu, rs0, 2);
        rs1 += __shfl_xor_sync(0xffffffffu, rs1, 1);
        rs1 += __shfl_xor_sync(0xffffffffu, rs1, 2);
        l0r = l0r * corr0 + rs0;
        l1r = l1r * corr1 + rs1;

        #pragma unroll
        for (int nt = 0; nt < 8; ++nt) {
            o[nt][0] *= corr0;
            o[nt][1] *= corr0;
            o[nt][2] *= corr1;
            o[nt][3] *= corr1;
        }

        #pragma unroll
        for (int ks = 0; ks < 4; ++ks) {
            uint32_t vf[8][2];
            #pragma unroll
            for (int ntp = 0; ntp < 4; ++ntp) {
                uint32_t t0, t1, t2, t3;
                ldsm_x4(t0, t1, t2, t3, sV_b + offKV + (uint32_t)(ntp * 16 * 144 + ks * 32));
                vf[2 * ntp][0] = t0; vf[2 * ntp][1] = t1;
                vf[2 * ntp + 1][0] = t2; vf[2 * ntp + 1][1] = t3;
            }
            #pragma unroll
            for (int nt = 0; nt < 8; ++nt)
                mma_f16_16n8k16(o[nt], pf[ks], vf[nt]);
        }
    }

    const int b = bh >> 4;
    const int h = bh & 15;
    const float inv0 = 1.0f / l0r;
    const float inv1 = 1.0f / l1r;
    #pragma unroll
    for (int nt = 0; nt < 8; ++nt) {
        const int a = nt * 8 + qd * 2;
        *(uint32_t*)&g_zh[(((size_t)b * Sn + grow0) * Hn + h) * An + a] =
            pack_h2(o[nt][0] * inv0, o[nt][1] * inv0);
        *(uint32_t*)&g_zh[(((size_t)b * Sn + grow1) * Hn + h) * An + a] =
            pack_h2(o[nt][2] * inv1, o[nt][3] * inv1);
    }
}

// ---------------------------------------------------------------------------
extern "C" void kernel_launch(void* const* d_in, const int* in_sizes, int n_in,
                              void* d_out, int out_size)
{
    const float* residual = (const float*)d_in[0];
    const float* Wq = (const float*)d_in[1];
    const float* Wk = (const float*)d_in[2];
    const float* Wv = (const float*)d_in[3];
    const float* Wo = (const float*)d_in[4];
    const float* bq = (const float*)d_in[5];
    const float* bk = (const float*)d_in[6];
    const float* bv = (const float*)d_in[7];
    const float* bo = (const float*)d_in[8];
    float* out = (float*)d_out;

    cudaFuncSetAttribute(flash_mma_kernel, cudaFuncAttributeMaxDynamicSharedMemorySize,
                         FLASH_SMEM_BYTES);
    cudaFuncSetAttribute(gemm_mma_kernel<0>, cudaFuncAttributeMaxDynamicSharedMemorySize,
                         GEMM_SMEM);
    cudaFuncSetAttribute(gemm_mma_kernel<1>, cudaFuncAttributeMaxDynamicSharedMemorySize,
                         GEMM_SMEM);

    // 0) fp16 prepass: residual convert + fused weight transposes (2 launches)
    conv_resid_kernel<<<1024, 256>>>(residual);
    transpose_w_kernel<<<dim3(32, 2, 64), dim3(32, 8)>>>(Wq, Wk, Wv, Wo);

    // 1) QKV projections (R15-proven: 128 threads, 64x64 warp tiles, 3 CTAs/SM)
    gemm_mma_kernel<0><<<dim3(HA / 128, Mrows / 128, 3), 128, GEMM_SMEM>>>(
        bq, bk, bv, nullptr);

    // 2) Causal flash attention (R15-proven)
    flash_mma_kernel<<<dim3(Sn / 64, Bn * Hn), 128, FLASH_SMEM_BYTES>>>();

    // 3) Output projection
    gemm_mma_kernel<1><<<dim3(Dn / 128, Mrows / 128, 1), 128, GEMM_SMEM>>>(
        bo, nullptr, nullptr, out);
}